// round 13
// baseline (speedup 1.0000x reference)
#include <cuda_runtime.h>
#include <cuda_fp16.h>

// RoIAlign (torchvision aligned=True, sampling_ratio=2) — two-pass:
//  1) transpose x [B,C,H,W] f32 -> g_xt [B,H,W,C] f16, batches in REVERSE
//     order so batch 0 (read first by the gather) is last-written = L2-hot.
//  2) gather: block = one box (36 positions, 8 warps). 1-D interp tables
//     precomputed once per block in smem; warp covers all 256 channels per
//     corner via one LDG.128/lane.

#define B_    8
#define N_    64
#define C_    256
#define C2_   (C_ / 2)
#define H_    128
#define W_    128
#define HW_   (H_ * W_)
#define OUT_H 6
#define OUT_W 6
#define NPOS  36
#define TPB   256            // 8 warps

// 8 * 16384 * 256 halves = 64 MB scratch (__device__ global: allowed)
__device__ __half g_xt[(size_t)B_ * HW_ * C_];

// ---------------------------------------------------------------------------
// Pass 1: transpose [C, HW] f32 tile (64ch x 32sp) -> [HW, C] f16.
// Reverse batch order: b = 7 - blockIdx.z.
// ---------------------------------------------------------------------------
__global__ void __launch_bounds__(256)
transpose_kernel(const float* __restrict__ x)
{
    __shared__ float sm[64][33];

    const int b  = (B_ - 1) - blockIdx.z;
    const int c0 = blockIdx.y * 64;
    const int s0 = blockIdx.x * 32;
    const int tid = threadIdx.x;
    const int tx = tid & 31;
    const int ty = tid >> 5;

    const float* src = x + ((size_t)b * C_ + c0) * HW_ + s0;
    #pragma unroll
    for (int r = 0; r < 8; r++) {
        int cl = ty + 8 * r;
        sm[cl][tx] = src[(size_t)cl * HW_ + tx];
    }
    __syncthreads();

    const int sp = tid >> 3;
    const int g  = tid & 7;

    uint4 v;
    __half2* h2 = (__half2*)&v;
    #pragma unroll
    for (int k = 0; k < 4; k++) {
        float a = sm[8 * g + 2 * k + 0][sp];
        float c = sm[8 * g + 2 * k + 1][sp];
        h2[k] = __floats2half2_rn(a, c);
    }

    uint4* dst = (uint4*)g_xt;   // pixel stride = 32 uint4
    dst[((size_t)b * HW_ + s0 + sp) * 32 + (c0 >> 3) + g] = v;
}

// ---------------------------------------------------------------------------
// Pass 2: gather. blockIdx.x = bn. 1-D interp precomputed into smem:
//   y entry j = oh*2 + iy : yLo32/yHi32 = row*W*32, wy0/wy1
//   x entry k = ow*2 + ix : xLo32/xHi32 = col*32,   wx0q/wx1q (0.25 folded)
// Per position: warp-uniform LDS broadcasts + IADD addresses + 16 LDG.128.
// ---------------------------------------------------------------------------
__global__ void __launch_bounds__(TPB)
gather_kernel(const float* __restrict__ boxes, float* __restrict__ out)
{
    __shared__ float tile[NPOS][C_ + 2];   // 37 KB
    __shared__ int   sYLo[12], sYHi[12], sXLo[12], sXHi[12];
    __shared__ float sWy0[12], sWy1[12], sWx0[12], sWx1[12];

    const int bn   = blockIdx.x;          // b*64 + n
    const int b    = bn >> 6;
    const int tid  = threadIdx.x;
    const int lane = tid & 31;
    const int w    = tid >> 5;

    const float* box = boxes + bn * 4;

    // ---- once-per-block 1-D interpolation tables (threads 0..23) ----
    if (tid < 24) {
        const bool isY = tid < 12;
        const int  j   = isY ? tid : tid - 12;
        const int  bin = j >> 1;             // oh or ow
        const int  i   = j & 1;              // sample index in bin
        const int  SZ  = isY ? H_ : W_;      // == 128 both

        float c1 = __ldg(box + (isY ? 1 : 0)) - 0.5f;
        float c2 = __ldg(box + (isY ? 3 : 2)) - 0.5f;
        float bs = (c2 - c1) * (1.0f / 6.0f);

        float cc = c1 + ((float)bin + ((float)i + 0.5f) * 0.5f) * bs;
        bool  vv = (cc >= -1.0f) && (cc <= (float)SZ);
        float cp = fmaxf(cc, 0.0f);
        int   lo = (int)floorf(cp);
        bool  ee = (lo >= SZ - 1);
        int   l  = ee ? (SZ - 1) : lo;
        int   h  = ee ? (SZ - 1) : (lo + 1);
        float fr = ee ? 0.0f : (cp - (float)lo);
        float w1 = vv ? fr : 0.0f;
        float w0 = vv ? (1.0f - fr) : 0.0f;

        if (isY) {
            sYLo[j] = l * (W_ * 32);         // pre-scaled row offset (uint4)
            sYHi[j] = h * (W_ * 32);
            sWy0[j] = w0;
            sWy1[j] = w1;
        } else {
            sXLo[j] = l * 32;                // pre-scaled col offset (uint4)
            sXHi[j] = h * 32;
            sWx0[j] = w0 * 0.25f;            // fold sample average (exact)
            sWx1[j] = w1 * 0.25f;
        }
    }
    __syncthreads();

    const uint4* xt4 = (const uint4*)g_xt + (size_t)b * HW_ * 32 + lane;

    #pragma unroll
    for (int pl = 0; pl < 5; pl++) {
        const int pos = w + 8 * pl;                // warp-uniform
        if (pos >= NPOS) break;
        const int oh = pos / 6;
        const int ow = pos - 6 * oh;
        const int j0 = oh * 2;
        const int k0 = ow * 2;

        float acc[8];
        #pragma unroll
        for (int k = 0; k < 8; k++) acc[k] = 0.0f;

        #pragma unroll
        for (int iy = 0; iy < 2; iy++) {
            const int   yLo = sYLo[j0 + iy], yHi = sYHi[j0 + iy];
            const float wy0 = sWy0[j0 + iy], wy1 = sWy1[j0 + iy];
            #pragma unroll
            for (int ix = 0; ix < 2; ix++) {
                const int   xLo = sXLo[k0 + ix], xHi = sXHi[k0 + ix];
                const float wx0 = sWx0[k0 + ix], wx1 = sWx1[k0 + ix];

                uint4 v00 = __ldg(xt4 + (yLo + xLo));
                uint4 v01 = __ldg(xt4 + (yLo + xHi));
                uint4 v10 = __ldg(xt4 + (yHi + xLo));
                uint4 v11 = __ldg(xt4 + (yHi + xHi));

                const float w00 = wy0 * wx0;
                const float w01 = wy0 * wx1;
                const float w10 = wy1 * wx0;
                const float w11 = wy1 * wx1;

                const uint4* vs[4] = { &v00, &v01, &v10, &v11 };
                const float  ws[4] = { w00, w01, w10, w11 };
                #pragma unroll
                for (int c4 = 0; c4 < 4; c4++) {
                    const __half2* h = (const __half2*)vs[c4];
                    const float wgt = ws[c4];
                    #pragma unroll
                    for (int j = 0; j < 4; j++) {
                        float2 f = __half22float2(h[j]);
                        acc[2 * j + 0] += wgt * f.x;
                        acc[2 * j + 1] += wgt * f.y;
                    }
                }
            }
        }

        float2* row = (float2*)&tile[pos][0];     // stride 258 -> 8B aligned
        #pragma unroll
        for (int j = 0; j < 4; j++) {
            row[4 * lane + j] = make_float2(acc[2 * j], acc[2 * j + 1]);
        }
    }
    __syncthreads();

    // Output: 9216 contiguous floats; increment-carry de-linearization
    // (256 = 7*36 + 4), 36 coalesced stores per thread.
    float* obase = out + (size_t)bn * (C_ * NPOS);
    int c = tid / 36;
    int p = tid - 36 * c;
    #pragma unroll
    for (int i = 0; i < NPOS; i++) {
        obase[i * TPB + tid] = tile[p][c];
        c += 7; p += 4;
        if (p >= 36) { p -= 36; c += 1; }
    }
}

extern "C" void kernel_launch(void* const* d_in, const int* in_sizes, int n_in,
                              void* d_out, int out_size)
{
    const float* x     = (const float*)d_in[0];
    const float* boxes = (const float*)d_in[1];
    float*       out   = (float*)d_out;

    dim3 tgrid(HW_ / 32, C_ / 64, B_);      // 512 x 4 x 8
    transpose_kernel<<<tgrid, 256>>>(x);
    gather_kernel<<<B_ * N_, TPB>>>(boxes, out);
}

// round 14
// speedup vs baseline: 1.0006x; 1.0006x over previous
#include <cuda_runtime.h>
#include <cuda_fp16.h>

// RoIAlign (torchvision aligned=True, sampling_ratio=2) — two-pass:
//  1) transpose x [B,C,H,W] f32 -> g_xt [B,H,W,C] f16 (uint4 stores),
//     batches in reverse order (batch 0, read first by gather, stays L2-hot)
//  2) gather: block = one box (36 positions, 8 warps, grid 512 = one wave).
//     Warp covers all 256 channels per corner via one LDG.128/lane.
//     x-direction lerp in half2 (HMUL2/HFMA2), y-lerp + accumulate in f32.

#define B_    8
#define N_    64
#define C_    256
#define C2_   (C_ / 2)
#define H_    128
#define W_    128
#define HW_   (H_ * W_)
#define OUT_H 6
#define OUT_W 6
#define NPOS  36
#define TPB   256            // 8 warps

// 8 * 16384 * 256 halves = 64 MB scratch (__device__ global: allowed)
__device__ __half g_xt[(size_t)B_ * HW_ * C_];

// ---------------------------------------------------------------------------
// Pass 1: transpose [C, HW] f32 tile (64ch x 32sp) -> [HW, C] f16.
// ---------------------------------------------------------------------------
__global__ void __launch_bounds__(256)
transpose_kernel(const float* __restrict__ x)
{
    __shared__ float sm[64][33];

    const int b  = (B_ - 1) - blockIdx.z;   // reverse: batch 0 written last
    const int c0 = blockIdx.y * 64;
    const int s0 = blockIdx.x * 32;
    const int tid = threadIdx.x;
    const int tx = tid & 31;
    const int ty = tid >> 5;

    const float* src = x + ((size_t)b * C_ + c0) * HW_ + s0;
    #pragma unroll
    for (int r = 0; r < 8; r++) {
        int cl = ty + 8 * r;
        sm[cl][tx] = src[(size_t)cl * HW_ + tx];
    }
    __syncthreads();

    const int sp = tid >> 3;
    const int g  = tid & 7;

    uint4 v;
    __half2* h2 = (__half2*)&v;
    #pragma unroll
    for (int k = 0; k < 4; k++) {
        float a = sm[8 * g + 2 * k + 0][sp];
        float c = sm[8 * g + 2 * k + 1][sp];
        h2[k] = __floats2half2_rn(a, c);
    }

    uint4* dst = (uint4*)g_xt;   // pixel stride = 32 uint4
    dst[((size_t)b * HW_ + s0 + sp) * 32 + (c0 >> 3) + g] = v;
}

// ---------------------------------------------------------------------------
// Pass 2: gather. blockIdx.x = bn (one box). Warp w handles positions
// w, w+8, ... (<36). Lane l covers channels 8l..8l+7 (one uint4 per corner).
// ---------------------------------------------------------------------------
__global__ void __launch_bounds__(TPB)
gather_kernel(const float* __restrict__ boxes, float* __restrict__ out)
{
    __shared__ float tile[NPOS][C_ + 2];   // row stride 258 floats (37 KB)

    const int bn   = blockIdx.x;          // b*64 + n
    const int b    = bn >> 6;
    const int tid  = threadIdx.x;
    const int lane = tid & 31;
    const int w    = tid >> 5;

    const float* box = boxes + bn * 4;
    const float bx1 = __ldg(box + 0) - 0.5f;
    const float by1 = __ldg(box + 1) - 0.5f;
    const float bx2 = __ldg(box + 2) - 0.5f;
    const float by2 = __ldg(box + 3) - 0.5f;
    const float bw = (bx2 - bx1) * (1.0f / OUT_W);
    const float bh = (by2 - by1) * (1.0f / OUT_H);

    const uint4* xt4 = (const uint4*)g_xt + (size_t)b * HW_ * 32 + lane;

    #pragma unroll
    for (int pl = 0; pl < 5; pl++) {
        const int pos = w + 8 * pl;                // warp-uniform
        if (pos >= NPOS) break;
        const int oh = pos / 6;
        const int ow = pos - 6 * oh;

        int     yl[2], yh[2], xl[2], xh[2];
        float   wy0[2], wy1[2];
        __half2 wx0h[2], wx1h[2];
        #pragma unroll
        for (int i = 0; i < 2; i++) {
            float yy = by1 + ((float)oh + ((float)i + 0.5f) * 0.5f) * bh;
            bool  vy = (yy >= -1.0f) && (yy <= (float)H_);
            float cy = fmaxf(yy, 0.0f);
            int   lo = (int)floorf(cy);
            bool  ey = (lo >= H_ - 1);
            yl[i] = ey ? (H_ - 1) : lo;
            yh[i] = ey ? (H_ - 1) : (lo + 1);
            float fy = ey ? 0.0f : (cy - (float)lo);
            wy1[i] = vy ? fy : 0.0f;
            wy0[i] = vy ? (1.0f - fy) : 0.0f;

            float xx = bx1 + ((float)ow + ((float)i + 0.5f) * 0.5f) * bw;
            bool  vx = (xx >= -1.0f) && (xx <= (float)W_);
            float cx = fmaxf(xx, 0.0f);
            int   lx = (int)floorf(cx);
            bool  ex = (lx >= W_ - 1);
            xl[i] = ex ? (W_ - 1) : lx;
            xh[i] = ex ? (W_ - 1) : (lx + 1);
            float fx = ex ? 0.0f : (cx - (float)lx);
            // fold the 0.25 sample-average into the fp16 x-weights (exact /4)
            float fx1 = vx ? (fx * 0.25f) : 0.0f;
            float fx0 = vx ? ((1.0f - fx) * 0.25f) : 0.0f;
            wx0h[i] = __float2half2_rn(fx0);
            wx1h[i] = __float2half2_rn(fx1);
        }

        float acc[8];
        #pragma unroll
        for (int k = 0; k < 8; k++) acc[k] = 0.0f;

        #pragma unroll
        for (int iy = 0; iy < 2; iy++) {
            const int   rLo = yl[iy] * W_ * 32;
            const int   rHi = yh[iy] * W_ * 32;
            const float wyl = wy0[iy];
            const float wyh = wy1[iy];
            #pragma unroll
            for (int ix = 0; ix < 2; ix++) {
                const int cLo = xl[ix] * 32;
                const int cHi = xh[ix] * 32;

                uint4 a = __ldg(xt4 + (rLo + cLo));
                uint4 c = __ldg(xt4 + (rLo + cHi));
                uint4 d = __ldg(xt4 + (rHi + cLo));
                uint4 e = __ldg(xt4 + (rHi + cHi));

                const __half2* ha = (const __half2*)&a;
                const __half2* hc = (const __half2*)&c;
                const __half2* hd = (const __half2*)&d;
                const __half2* he = (const __half2*)&e;
                const __half2 w0 = wx0h[ix];
                const __half2 w1 = wx1h[ix];

                #pragma unroll
                for (int j = 0; j < 4; j++) {
                    // x-lerp in fp16 (2 ops), y-lerp in f32
                    __half2 rl = __hfma2(hc[j], w1, __hmul2(ha[j], w0));
                    __half2 rh = __hfma2(he[j], w1, __hmul2(hd[j], w0));
                    float2 fl = __half22float2(rl);
                    float2 fh = __half22float2(rh);
                    acc[2 * j + 0] += wyl * fl.x + wyh * fh.x;
                    acc[2 * j + 1] += wyl * fl.y + wyh * fh.y;
                }
            }
        }

        float2* row = (float2*)&tile[pos][0];     // stride 258 -> 8B aligned
        #pragma unroll
        for (int j = 0; j < 4; j++) {
            row[4 * lane + j] = make_float2(acc[2 * j], acc[2 * j + 1]);
        }
    }
    __syncthreads();

    // Output: 9216 contiguous floats; increment-carry de-linearization
    // (256 = 7*36 + 4), 36 coalesced stores per thread.
    float* obase = out + (size_t)bn * (C_ * NPOS);
    int c = tid / 36;
    int p = tid - 36 * c;
    #pragma unroll
    for (int i = 0; i < NPOS; i++) {
        obase[i * TPB + tid] = tile[p][c];
        c += 7; p += 4;
        if (p >= 36) { p -= 36; c += 1; }
    }
}

extern "C" void kernel_launch(void* const* d_in, const int* in_sizes, int n_in,
                              void* d_out, int out_size)
{
    const float* x     = (const float*)d_in[0];
    const float* boxes = (const float*)d_in[1];
    float*       out   = (float*)d_out;

    dim3 tgrid(HW_ / 32, C_ / 64, B_);      // 512 x 4 x 8
    transpose_kernel<<<tgrid, 256>>>(x);
    gather_kernel<<<B_ * N_, TPB>>>(boxes, out);
}

// round 15
// speedup vs baseline: 1.0440x; 1.0435x over previous
#include <cuda_runtime.h>
#include <cuda_fp16.h>

// RoIAlign (torchvision aligned=True, sampling_ratio=2) — two-pass, best
// measured composition:
//  1) transpose x [B,C,H,W] f32 -> g_xt [B,H,W,C] f16, forward batch order,
//     uint4 (8-channel) stores                               [R12: ~31.8us]
//  2) gather: grid 1024 = (bn, oh-half), 192 thr, 3 pos/warp; warp covers
//     all 256 channels per corner via one LDG.128/lane       [R6: ~20.5us]
//     0.25 sample-average folded into wx weights (exact).

#define B_    8
#define N_    64
#define C_    256
#define C2_   (C_ / 2)
#define H_    128
#define W_    128
#define HW_   (H_ * W_)
#define OUT_H 6
#define OUT_W 6
#define NPOS  36
#define PPB   18             // positions per gather block (half a box)
#define WPB   6              // warps per gather block
#define TPB   (WPB * 32)     // 192 threads

// 8 * 16384 * 256 halves = 64 MB scratch (__device__ global: allowed)
__device__ __half g_xt[(size_t)B_ * HW_ * C_];

// ---------------------------------------------------------------------------
// Pass 1: transpose [C, HW] f32 tile (64ch x 32sp) -> [HW, C] f16.
// Reads: 8 x 128B coalesced per warp. Writes: one uint4 (8 f16 ch) per
// thread. DRAM-bound (~6 TB/s).
// ---------------------------------------------------------------------------
__global__ void __launch_bounds__(256)
transpose_kernel(const float* __restrict__ x)
{
    __shared__ float sm[64][33];

    const int b  = blockIdx.z;
    const int c0 = blockIdx.y * 64;
    const int s0 = blockIdx.x * 32;
    const int tid = threadIdx.x;
    const int tx = tid & 31;
    const int ty = tid >> 5;

    const float* src = x + ((size_t)b * C_ + c0) * HW_ + s0;
    #pragma unroll
    for (int r = 0; r < 8; r++) {
        int cl = ty + 8 * r;
        sm[cl][tx] = src[(size_t)cl * HW_ + tx];
    }
    __syncthreads();

    const int sp = tid >> 3;
    const int g  = tid & 7;

    uint4 v;
    __half2* h2 = (__half2*)&v;
    #pragma unroll
    for (int k = 0; k < 4; k++) {
        float a = sm[8 * g + 2 * k + 0][sp];
        float c = sm[8 * g + 2 * k + 1][sp];
        h2[k] = __floats2half2_rn(a, c);
    }

    uint4* dst = (uint4*)g_xt;   // pixel stride = 32 uint4
    dst[((size_t)b * HW_ + s0 + sp) * 32 + (c0 >> 3) + g] = v;
}

// ---------------------------------------------------------------------------
// Pass 2: gather. blockIdx.x = bn*2 + half. Warp w handles local positions
// w, w+6, w+12 of its 18. Lane l accumulates channels 8l..8l+7 via one
// uint4 (8 fp16) per corner -> 512B fully-coalesced warp transactions.
// ---------------------------------------------------------------------------
__global__ void __launch_bounds__(TPB)
gather_kernel(const float* __restrict__ boxes, float* __restrict__ out)
{
    __shared__ float tile[PPB][C_ + 2];   // row stride 258 floats

    const int blk  = blockIdx.x;
    const int bn   = blk >> 1;            // b*64 + n
    const int half = blk & 1;             // oh rows 0-2 or 3-5
    const int b    = bn >> 6;
    const int tid  = threadIdx.x;
    const int lane = tid & 31;
    const int w    = tid >> 5;

    const float* box = boxes + bn * 4;
    const float bx1 = __ldg(box + 0) - 0.5f;
    const float by1 = __ldg(box + 1) - 0.5f;
    const float bx2 = __ldg(box + 2) - 0.5f;
    const float by2 = __ldg(box + 3) - 0.5f;
    const float bw = (bx2 - bx1) * (1.0f / OUT_W);
    const float bh = (by2 - by1) * (1.0f / OUT_H);

    const uint4* xt4 = (const uint4*)g_xt + (size_t)b * HW_ * 32 + lane;

    #pragma unroll
    for (int pl = 0; pl < 3; pl++) {
        const int pos  = w + 6 * pl;               // 0..17 local
        const int gpos = half * PPB + pos;         // 0..35 global
        const int oh = gpos / 6;
        const int ow = gpos - 6 * oh;

        int   yl[2], yh[2], xl[2], xh[2];
        float wy0[2], wy1[2], wx0[2], wx1[2];
        #pragma unroll
        for (int i = 0; i < 2; i++) {
            float yy = by1 + ((float)oh + ((float)i + 0.5f) * 0.5f) * bh;
            bool  vy = (yy >= -1.0f) && (yy <= (float)H_);
            float cy = fmaxf(yy, 0.0f);
            int   lo = (int)floorf(cy);
            bool  ey = (lo >= H_ - 1);
            yl[i] = ey ? (H_ - 1) : lo;
            yh[i] = ey ? (H_ - 1) : (lo + 1);
            float fy = ey ? 0.0f : (cy - (float)lo);
            wy1[i] = vy ? fy : 0.0f;
            wy0[i] = vy ? (1.0f - fy) : 0.0f;

            float xx = bx1 + ((float)ow + ((float)i + 0.5f) * 0.5f) * bw;
            bool  vx = (xx >= -1.0f) && (xx <= (float)W_);
            float cx = fmaxf(xx, 0.0f);
            int   lx = (int)floorf(cx);
            bool  ex = (lx >= W_ - 1);
            xl[i] = ex ? (W_ - 1) : lx;
            xh[i] = ex ? (W_ - 1) : (lx + 1);
            float fx = ex ? 0.0f : (cx - (float)lx);
            // fold the 0.25 sample average (exact: power of two)
            wx1[i] = vx ? (fx * 0.25f) : 0.0f;
            wx0[i] = vx ? ((1.0f - fx) * 0.25f) : 0.0f;
        }

        float acc[8];
        #pragma unroll
        for (int k = 0; k < 8; k++) acc[k] = 0.0f;

        #pragma unroll
        for (int iy = 0; iy < 2; iy++) {
            #pragma unroll
            for (int ix = 0; ix < 2; ix++) {
                const int p00 = (yl[iy] * W_ + xl[ix]) * 32;
                const int p01 = (yl[iy] * W_ + xh[ix]) * 32;
                const int p10 = (yh[iy] * W_ + xl[ix]) * 32;
                const int p11 = (yh[iy] * W_ + xh[ix]) * 32;
                const float w00 = wy0[iy] * wx0[ix];
                const float w01 = wy0[iy] * wx1[ix];
                const float w10 = wy1[iy] * wx0[ix];
                const float w11 = wy1[iy] * wx1[ix];

                uint4 v00 = __ldg(xt4 + p00);
                uint4 v01 = __ldg(xt4 + p01);
                uint4 v10 = __ldg(xt4 + p10);
                uint4 v11 = __ldg(xt4 + p11);

                const uint4* vs[4] = { &v00, &v01, &v10, &v11 };
                const float  ws[4] = { w00, w01, w10, w11 };
                #pragma unroll
                for (int c4 = 0; c4 < 4; c4++) {
                    const __half2* h = (const __half2*)vs[c4];
                    const float wgt = ws[c4];
                    #pragma unroll
                    for (int j = 0; j < 4; j++) {
                        float2 f = __half22float2(h[j]);
                        acc[2 * j + 0] += wgt * f.x;
                        acc[2 * j + 1] += wgt * f.y;
                    }
                }
            }
        }

        float2* row = (float2*)&tile[pos][0];     // stride 258 -> 8B aligned
        #pragma unroll
        for (int j = 0; j < 4; j++) {
            row[4 * lane + j] = make_float2(acc[2 * j], acc[2 * j + 1]);
        }
    }
    __syncthreads();

    // Output slab: for each channel c, 18 contiguous floats at c*36 + half*18.
    // e = i*192 + tid; c = e/18, p = e%18 via increment-carry (192 = 10*18+12).
    float* obase = out + (size_t)bn * (C_ * NPOS) + half * PPB;
    int c = tid / PPB;
    int p = tid - PPB * c;
    #pragma unroll
    for (int i = 0; i < (C_ * PPB) / TPB; i++) {   // 24 iterations
        obase[c * NPOS + p] = tile[p][c];
        c += 10; p += 12;
        if (p >= PPB) { p -= PPB; c += 1; }
    }
}

extern "C" void kernel_launch(void* const* d_in, const int* in_sizes, int n_in,
                              void* d_out, int out_size)
{
    const float* x     = (const float*)d_in[0];
    const float* boxes = (const float*)d_in[1];
    float*       out   = (float*)d_out;

    dim3 tgrid(HW_ / 32, C_ / 64, B_);      // 512 x 4 x 8
    transpose_kernel<<<tgrid, 256>>>(x);
    gather_kernel<<<B_ * N_ * 2, TPB>>>(boxes, out);
}

// round 16
// speedup vs baseline: 1.1251x; 1.0776x over previous
#include <cuda_runtime.h>
#include <cuda_fp16.h>

// RoIAlign (torchvision aligned=True, sampling_ratio=2) — two-pass:
//  1) transpose x [B,C,H,W] f32 -> g_xt [B,H,W,C] f16. Input reads use
//     __ldcs (evict-first) so the touch-once 128MB read stream does NOT
//     evict the 64MB scratch from L2.
//  2) gather (R6/R15 shape): grid 1024 = (bn, oh-half), 192 thr, 3 pos/warp;
//     warp covers all 256 channels per corner via one LDG.128/lane; scratch
//     reads hit L2. Output stores use __stcs (touch-once).

#define B_    8
#define N_    64
#define C_    256
#define C2_   (C_ / 2)
#define H_    128
#define W_    128
#define HW_   (H_ * W_)
#define OUT_H 6
#define OUT_W 6
#define NPOS  36
#define PPB   18             // positions per gather block (half a box)
#define WPB   6              // warps per gather block
#define TPB   (WPB * 32)     // 192 threads

// 8 * 16384 * 256 halves = 64 MB scratch (__device__ global: allowed)
__device__ __half g_xt[(size_t)B_ * HW_ * C_];

// ---------------------------------------------------------------------------
// Pass 1: transpose [C, HW] f32 tile (64ch x 32sp) -> [HW, C] f16.
// ---------------------------------------------------------------------------
__global__ void __launch_bounds__(256)
transpose_kernel(const float* __restrict__ x)
{
    __shared__ float sm[64][33];

    const int b  = blockIdx.z;
    const int c0 = blockIdx.y * 64;
    const int s0 = blockIdx.x * 32;
    const int tid = threadIdx.x;
    const int tx = tid & 31;
    const int ty = tid >> 5;

    const float* src = x + ((size_t)b * C_ + c0) * HW_ + s0;
    #pragma unroll
    for (int r = 0; r < 8; r++) {
        int cl = ty + 8 * r;
        sm[cl][tx] = __ldcs(src + (size_t)cl * HW_ + tx);   // streaming read
    }
    __syncthreads();

    const int sp = tid >> 3;
    const int g  = tid & 7;

    uint4 v;
    __half2* h2 = (__half2*)&v;
    #pragma unroll
    for (int k = 0; k < 4; k++) {
        float a = sm[8 * g + 2 * k + 0][sp];
        float c = sm[8 * g + 2 * k + 1][sp];
        h2[k] = __floats2half2_rn(a, c);
    }

    uint4* dst = (uint4*)g_xt;   // pixel stride = 32 uint4; normal (resident)
    dst[((size_t)b * HW_ + s0 + sp) * 32 + (c0 >> 3) + g] = v;
}

// ---------------------------------------------------------------------------
// Pass 2: gather. blockIdx.x = bn*2 + half. Warp w handles local positions
// w, w+6, w+12 of its 18. Lane l accumulates channels 8l..8l+7 via one
// uint4 (8 fp16) per corner -> 512B fully-coalesced warp transactions.
// ---------------------------------------------------------------------------
__global__ void __launch_bounds__(TPB)
gather_kernel(const float* __restrict__ boxes, float* __restrict__ out)
{
    __shared__ float tile[PPB][C_ + 2];   // row stride 258 floats

    const int blk  = blockIdx.x;
    const int bn   = blk >> 1;            // b*64 + n
    const int half = blk & 1;             // oh rows 0-2 or 3-5
    const int b    = bn >> 6;
    const int tid  = threadIdx.x;
    const int lane = tid & 31;
    const int w    = tid >> 5;

    const float* box = boxes + bn * 4;
    const float bx1 = __ldg(box + 0) - 0.5f;
    const float by1 = __ldg(box + 1) - 0.5f;
    const float bx2 = __ldg(box + 2) - 0.5f;
    const float by2 = __ldg(box + 3) - 0.5f;
    const float bw = (bx2 - bx1) * (1.0f / OUT_W);
    const float bh = (by2 - by1) * (1.0f / OUT_H);

    const uint4* xt4 = (const uint4*)g_xt + (size_t)b * HW_ * 32 + lane;

    #pragma unroll
    for (int pl = 0; pl < 3; pl++) {
        const int pos  = w + 6 * pl;               // 0..17 local
        const int gpos = half * PPB + pos;         // 0..35 global
        const int oh = gpos / 6;
        const int ow = gpos - 6 * oh;

        int   yl[2], yh[2], xl[2], xh[2];
        float wy0[2], wy1[2], wx0[2], wx1[2];
        #pragma unroll
        for (int i = 0; i < 2; i++) {
            float yy = by1 + ((float)oh + ((float)i + 0.5f) * 0.5f) * bh;
            bool  vy = (yy >= -1.0f) && (yy <= (float)H_);
            float cy = fmaxf(yy, 0.0f);
            int   lo = (int)floorf(cy);
            bool  ey = (lo >= H_ - 1);
            yl[i] = ey ? (H_ - 1) : lo;
            yh[i] = ey ? (H_ - 1) : (lo + 1);
            float fy = ey ? 0.0f : (cy - (float)lo);
            wy1[i] = vy ? fy : 0.0f;
            wy0[i] = vy ? (1.0f - fy) : 0.0f;

            float xx = bx1 + ((float)ow + ((float)i + 0.5f) * 0.5f) * bw;
            bool  vx = (xx >= -1.0f) && (xx <= (float)W_);
            float cx = fmaxf(xx, 0.0f);
            int   lx = (int)floorf(cx);
            bool  ex = (lx >= W_ - 1);
            xl[i] = ex ? (W_ - 1) : lx;
            xh[i] = ex ? (W_ - 1) : (lx + 1);
            float fx = ex ? 0.0f : (cx - (float)lx);
            // fold the 0.25 sample average (exact: power of two)
            wx1[i] = vx ? (fx * 0.25f) : 0.0f;
            wx0[i] = vx ? ((1.0f - fx) * 0.25f) : 0.0f;
        }

        float acc[8];
        #pragma unroll
        for (int k = 0; k < 8; k++) acc[k] = 0.0f;

        #pragma unroll
        for (int iy = 0; iy < 2; iy++) {
            #pragma unroll
            for (int ix = 0; ix < 2; ix++) {
                const int p00 = (yl[iy] * W_ + xl[ix]) * 32;
                const int p01 = (yl[iy] * W_ + xh[ix]) * 32;
                const int p10 = (yh[iy] * W_ + xl[ix]) * 32;
                const int p11 = (yh[iy] * W_ + xh[ix]) * 32;
                const float w00 = wy0[iy] * wx0[ix];
                const float w01 = wy0[iy] * wx1[ix];
                const float w10 = wy1[iy] * wx0[ix];
                const float w11 = wy1[iy] * wx1[ix];

                uint4 v00 = __ldg(xt4 + p00);
                uint4 v01 = __ldg(xt4 + p01);
                uint4 v10 = __ldg(xt4 + p10);
                uint4 v11 = __ldg(xt4 + p11);

                const uint4* vs[4] = { &v00, &v01, &v10, &v11 };
                const float  ws[4] = { w00, w01, w10, w11 };
                #pragma unroll
                for (int c4 = 0; c4 < 4; c4++) {
                    const __half2* h = (const __half2*)vs[c4];
                    const float wgt = ws[c4];
                    #pragma unroll
                    for (int j = 0; j < 4; j++) {
                        float2 f = __half22float2(h[j]);
                        acc[2 * j + 0] += wgt * f.x;
                        acc[2 * j + 1] += wgt * f.y;
                    }
                }
            }
        }

        float2* row = (float2*)&tile[pos][0];     // stride 258 -> 8B aligned
        #pragma unroll
        for (int j = 0; j < 4; j++) {
            row[4 * lane + j] = make_float2(acc[2 * j], acc[2 * j + 1]);
        }
    }
    __syncthreads();

    // Output slab: for each channel c, 18 contiguous floats at c*36 + half*18.
    // Streaming stores (touch-once) so the output doesn't evict the scratch.
    float* obase = out + (size_t)bn * (C_ * NPOS) + half * PPB;
    int c = tid / PPB;
    int p = tid - PPB * c;
    #pragma unroll
    for (int i = 0; i < (C_ * PPB) / TPB; i++) {   // 24 iterations
        __stcs(obase + c * NPOS + p, tile[p][c]);
        c += 10; p += 12;
        if (p >= PPB) { p -= PPB; c += 1; }
    }
}

extern "C" void kernel_launch(void* const* d_in, const int* in_sizes, int n_in,
                              void* d_out, int out_size)
{
    const float* x     = (const float*)d_in[0];
    const float* boxes = (const float*)d_in[1];
    float*       out   = (float*)d_out;

    dim3 tgrid(HW_ / 32, C_ / 64, B_);      // 512 x 4 x 8
    transpose_kernel<<<tgrid, 256>>>(x);
    gather_kernel<<<B_ * N_ * 2, TPB>>>(boxes, out);
}